// round 14
// baseline (speedup 1.0000x reference)
#include <cuda_runtime.h>
#include <cuda_bf16.h>
#include <cstddef>

// ---------------------------------------------------------------------------
// Problem constants
//   x: [8, 8192, 512] fp32, tokens M = 65536, D = 512, D_FF = 2048,
//   8 heads * dh=64, window = 32 (non-overlapping, block-local attention)
// ---------------------------------------------------------------------------
#define M_TOK   65536
#define D_MODEL 512
#define D_FF    2048
#define N_HEADS 8
#define D_HEAD  64
#define WINDOW  32
#define EPS_LN  1e-5f

// ---------------------------------------------------------------------------
// Device scratch (static device globals: allowed; no runtime allocation)
// ---------------------------------------------------------------------------
__device__ float g_q[M_TOK * D_MODEL];   // Q          ; reused for res2
__device__ float g_k[M_TOK * D_MODEL];   // K          ; reused for res1
__device__ float g_v[M_TOK * D_MODEL];   // V          ; reused for x1 (post-LN1)
__device__ float g_o[M_TOK * D_MODEL];   // attention output (pre-Wo)
__device__ float g_h[M_TOK * D_FF];      // FFN hidden

// ---------------------------------------------------------------------------
// SGEMM: C[M,N] = A[M,K] @ B[K,N] + bias (+ residual) (+ relu)
//   EPI 0: bias
//   EPI 1: bias + relu
//   EPI 2: bias + residual
// BM=BN=128, BK=16, 256 threads, 8x8 per thread.
// All M,N,K here are multiples of 128 -> no bounds checks.
// ---------------------------------------------------------------------------
#define BM 128
#define BN 128
#define BK 16
#define SPAD 136   // padded smem row length (conflict-free, float4-aligned)

template <int EPI>
__global__ __launch_bounds__(256, 2)
void sgemm_kernel(const float* __restrict__ A, const float* __restrict__ B,
                  const float* __restrict__ bias, const float* __restrict__ resid,
                  float* __restrict__ C, int M, int N, int K)
{
    __shared__ __align__(16) float As[BK][SPAD];  // stored transposed: As[k][m]
    __shared__ __align__(16) float Bs[BK][SPAD];  // Bs[k][n]

    const int tid = threadIdx.x;
    const int bm = blockIdx.y * BM;
    const int bn = blockIdx.x * BN;

    const int ty   = tid >> 4;        // 0..15
    const int tx   = tid & 15;        // 0..15
    const int row0 = ty * 8;          // 8 consecutive rows
    const int col0 = tx * 4;          // cols col0..+3 and col0+64..+67

    // A-tile load mapping: 128 rows x 16 cols, float4 along K
    const int ar = tid >> 2;          // 0..63
    const int ac = (tid & 3) * 4;     // 0,4,8,12
    // B-tile load mapping: 16 rows x 128 cols, float4 along N
    const int br = tid >> 5;          // 0..7
    const int bc = (tid & 31) * 4;    // 0..124

    float acc[8][8];
#pragma unroll
    for (int i = 0; i < 8; i++)
#pragma unroll
        for (int j = 0; j < 8; j++) acc[i][j] = 0.f;

    for (int kt = 0; kt < K; kt += BK) {
#pragma unroll
        for (int p = 0; p < 2; p++) {
            int r = ar + p * 64;
            float4 va = *reinterpret_cast<const float4*>(
                &A[(size_t)(bm + r) * K + kt + ac]);
            As[ac + 0][r] = va.x;
            As[ac + 1][r] = va.y;
            As[ac + 2][r] = va.z;
            As[ac + 3][r] = va.w;
        }
#pragma unroll
        for (int p = 0; p < 2; p++) {
            int r = br + p * 8;
            *reinterpret_cast<float4*>(&Bs[r][bc]) =
                *reinterpret_cast<const float4*>(
                    &B[(size_t)(kt + r) * N + bn + bc]);
        }
        __syncthreads();

#pragma unroll
        for (int k = 0; k < BK; k++) {
            float4 a0 = *reinterpret_cast<const float4*>(&As[k][row0]);
            float4 a1 = *reinterpret_cast<const float4*>(&As[k][row0 + 4]);
            float4 b0 = *reinterpret_cast<const float4*>(&Bs[k][col0]);
            float4 b1 = *reinterpret_cast<const float4*>(&Bs[k][col0 + 64]);
            float a[8] = {a0.x, a0.y, a0.z, a0.w, a1.x, a1.y, a1.z, a1.w};
            float b[8] = {b0.x, b0.y, b0.z, b0.w, b1.x, b1.y, b1.z, b1.w};
#pragma unroll
            for (int i = 0; i < 8; i++)
#pragma unroll
                for (int j = 0; j < 8; j++)
                    acc[i][j] = fmaf(a[i], b[j], acc[i][j]);
        }
        __syncthreads();
    }

    // Epilogue
    float bb[8];
#pragma unroll
    for (int j = 0; j < 4; j++) {
        bb[j]     = bias[bn + col0 + j];
        bb[4 + j] = bias[bn + col0 + 64 + j];
    }
#pragma unroll
    for (int i = 0; i < 8; i++) {
        size_t base = (size_t)(bm + row0 + i) * N + bn;
        float4 o0, o1;
        o0.x = acc[i][0] + bb[0]; o0.y = acc[i][1] + bb[1];
        o0.z = acc[i][2] + bb[2]; o0.w = acc[i][3] + bb[3];
        o1.x = acc[i][4] + bb[4]; o1.y = acc[i][5] + bb[5];
        o1.z = acc[i][6] + bb[6]; o1.w = acc[i][7] + bb[7];
        if (EPI == 2) {
            float4 r0 = *reinterpret_cast<const float4*>(&resid[base + col0]);
            float4 r1 = *reinterpret_cast<const float4*>(&resid[base + col0 + 64]);
            o0.x += r0.x; o0.y += r0.y; o0.z += r0.z; o0.w += r0.w;
            o1.x += r1.x; o1.y += r1.y; o1.z += r1.z; o1.w += r1.w;
        }
        if (EPI == 1) {
            o0.x = fmaxf(o0.x, 0.f); o0.y = fmaxf(o0.y, 0.f);
            o0.z = fmaxf(o0.z, 0.f); o0.w = fmaxf(o0.w, 0.f);
            o1.x = fmaxf(o1.x, 0.f); o1.y = fmaxf(o1.y, 0.f);
            o1.z = fmaxf(o1.z, 0.f); o1.w = fmaxf(o1.w, 0.f);
        }
        *reinterpret_cast<float4*>(&C[base + col0])      = o0;
        *reinterpret_cast<float4*>(&C[base + col0 + 64]) = o1;
    }
}

// ---------------------------------------------------------------------------
// Block-local window attention: one block per (window, head).
//   Q,K,V laid out as [token, 512] with head slice h*64..h*64+63.
//   scores = QK^T / sqrt(64), row-softmax, O = P V.
// ---------------------------------------------------------------------------
__global__ __launch_bounds__(256)
void attn_kernel(const float* __restrict__ Q, const float* __restrict__ K,
                 const float* __restrict__ V, float* __restrict__ O)
{
    __shared__ __align__(16) float qs[WINDOW * D_HEAD];
    __shared__ __align__(16) float ks[WINDOW * D_HEAD];
    __shared__ __align__(16) float vs[WINDOW * D_HEAD];
    __shared__ float sc[WINDOW][WINDOW + 1];

    const int tid = threadIdx.x;
    const int h   = blockIdx.x & (N_HEADS - 1);
    const int win = blockIdx.x >> 3;               // global window id (b*nW+n)
    const size_t t0 = (size_t)win * WINDOW;

    // Load Q/K/V tiles: 512 float4's each, 2 per thread
#pragma unroll
    for (int p = 0; p < 2; p++) {
        int v4 = tid + p * 256;        // 0..511
        int r  = v4 >> 4;              // 0..31
        int c4 = (v4 & 15) * 4;        // 0..60
        size_t gidx = (t0 + r) * D_MODEL + h * D_HEAD + c4;
        *reinterpret_cast<float4*>(&qs[r * D_HEAD + c4]) =
            *reinterpret_cast<const float4*>(&Q[gidx]);
        *reinterpret_cast<float4*>(&ks[r * D_HEAD + c4]) =
            *reinterpret_cast<const float4*>(&K[gidx]);
        *reinterpret_cast<float4*>(&vs[r * D_HEAD + c4]) =
            *reinterpret_cast<const float4*>(&V[gidx]);
    }
    __syncthreads();

    // Scores: 1024 entries, 4 per thread (same q-row, 4 consecutive k-rows)
    {
        int qr  = tid >> 3;            // 0..31
        int kr0 = (tid & 7) * 4;       // 0,4,...,28
        float s0 = 0.f, s1 = 0.f, s2 = 0.f, s3 = 0.f;
#pragma unroll
        for (int d = 0; d < D_HEAD; d += 4) {
            float4 qv = *reinterpret_cast<const float4*>(&qs[qr * D_HEAD + d]);
            float4 k0 = *reinterpret_cast<const float4*>(&ks[(kr0 + 0) * D_HEAD + d]);
            float4 k1 = *reinterpret_cast<const float4*>(&ks[(kr0 + 1) * D_HEAD + d]);
            float4 k2 = *reinterpret_cast<const float4*>(&ks[(kr0 + 2) * D_HEAD + d]);
            float4 k3 = *reinterpret_cast<const float4*>(&ks[(kr0 + 3) * D_HEAD + d]);
            s0 += qv.x * k0.x + qv.y * k0.y + qv.z * k0.z + qv.w * k0.w;
            s1 += qv.x * k1.x + qv.y * k1.y + qv.z * k1.z + qv.w * k1.w;
            s2 += qv.x * k2.x + qv.y * k2.y + qv.z * k2.z + qv.w * k2.w;
            s3 += qv.x * k3.x + qv.y * k3.y + qv.z * k3.z + qv.w * k3.w;
        }
        const float scale = 0.125f;    // 1/sqrt(64)
        sc[qr][kr0 + 0] = s0 * scale;
        sc[qr][kr0 + 1] = s1 * scale;
        sc[qr][kr0 + 2] = s2 * scale;
        sc[qr][kr0 + 3] = s3 * scale;
    }
    __syncthreads();

    // Softmax per row (rows are tiny: 32 entries; one thread per row)
    if (tid < WINDOW) {
        float mx = -1e30f;
#pragma unroll
        for (int j = 0; j < WINDOW; j++) mx = fmaxf(mx, sc[tid][j]);
        float s = 0.f;
#pragma unroll
        for (int j = 0; j < WINDOW; j++) {
            float e = __expf(sc[tid][j] - mx);
            sc[tid][j] = e;
            s += e;
        }
        float inv = 1.f / s;
#pragma unroll
        for (int j = 0; j < WINDOW; j++) sc[tid][j] *= inv;
    }
    __syncthreads();

    // O = P @ V : 512 float4 outputs, 2 per thread
#pragma unroll
    for (int p = 0; p < 2; p++) {
        int v4 = tid + p * 256;
        int qr = v4 >> 4;
        int c4 = (v4 & 15) * 4;
        float4 o = make_float4(0.f, 0.f, 0.f, 0.f);
#pragma unroll
        for (int kr = 0; kr < WINDOW; kr++) {
            float w = sc[qr][kr];
            float4 vv = *reinterpret_cast<const float4*>(&vs[kr * D_HEAD + c4]);
            o.x = fmaf(w, vv.x, o.x);
            o.y = fmaf(w, vv.y, o.y);
            o.z = fmaf(w, vv.z, o.z);
            o.w = fmaf(w, vv.w, o.w);
        }
        *reinterpret_cast<float4*>(&O[(t0 + qr) * D_MODEL + h * D_HEAD + c4]) = o;
    }
}

// ---------------------------------------------------------------------------
// LayerNorm over last dim (512). One warp per row, 8 rows per block.
// ---------------------------------------------------------------------------
__global__ __launch_bounds__(256)
void ln_kernel(const float* __restrict__ in, const float* __restrict__ g,
               const float* __restrict__ be, float* __restrict__ out)
{
    const int warp = threadIdx.x >> 5;
    const int lane = threadIdx.x & 31;
    const size_t row = (size_t)blockIdx.x * 8 + warp;
    const float* rp = in + row * D_MODEL;

    float4 xv[4];
    float s = 0.f, s2 = 0.f;
#pragma unroll
    for (int j = 0; j < 4; j++) {
        xv[j] = *reinterpret_cast<const float4*>(&rp[(lane + 32 * j) * 4]);
        s  += xv[j].x + xv[j].y + xv[j].z + xv[j].w;
        s2 += xv[j].x * xv[j].x + xv[j].y * xv[j].y +
              xv[j].z * xv[j].z + xv[j].w * xv[j].w;
    }
#pragma unroll
    for (int o = 16; o > 0; o >>= 1) {
        s  += __shfl_xor_sync(0xffffffffu, s,  o);
        s2 += __shfl_xor_sync(0xffffffffu, s2, o);
    }
    const float mu  = s * (1.f / D_MODEL);
    float var = s2 * (1.f / D_MODEL) - mu * mu;
    const float rs = rsqrtf(var + EPS_LN);

    float* op = out + row * D_MODEL;
#pragma unroll
    for (int j = 0; j < 4; j++) {
        int c = (lane + 32 * j) * 4;
        float4 gv = *reinterpret_cast<const float4*>(&g[c]);
        float4 bv = *reinterpret_cast<const float4*>(&be[c]);
        float4 y;
        y.x = (xv[j].x - mu) * rs * gv.x + bv.x;
        y.y = (xv[j].y - mu) * rs * gv.y + bv.y;
        y.z = (xv[j].z - mu) * rs * gv.z + bv.z;
        y.w = (xv[j].w - mu) * rs * gv.w + bv.w;
        *reinterpret_cast<float4*>(&op[c]) = y;
    }
}

// ---------------------------------------------------------------------------
// kernel_launch — graph-capturable: kernel launches on the default stream only
// ---------------------------------------------------------------------------
extern "C" void kernel_launch(void* const* d_in, const int* in_sizes, int n_in,
                              void* d_out, int out_size)
{
    const float* x   = (const float*)d_in[0];
    const float* Wq  = (const float*)d_in[1];
    const float* bq  = (const float*)d_in[2];
    const float* Wk  = (const float*)d_in[3];
    const float* bk  = (const float*)d_in[4];
    const float* Wv  = (const float*)d_in[5];
    const float* bv  = (const float*)d_in[6];
    const float* Wo  = (const float*)d_in[7];
    const float* bo  = (const float*)d_in[8];
    const float* g1  = (const float*)d_in[9];
    const float* be1 = (const float*)d_in[10];
    const float* W1  = (const float*)d_in[11];
    const float* b1  = (const float*)d_in[12];
    const float* W2  = (const float*)d_in[13];
    const float* b2  = (const float*)d_in[14];
    const float* g2  = (const float*)d_in[15];
    const float* be2 = (const float*)d_in[16];
    float* out = (float*)d_out;

    float *q, *k, *v, *o, *h;
    cudaGetSymbolAddress((void**)&q, g_q);
    cudaGetSymbolAddress((void**)&k, g_k);
    cudaGetSymbolAddress((void**)&v, g_v);
    cudaGetSymbolAddress((void**)&o, g_o);
    cudaGetSymbolAddress((void**)&h, g_h);

    // Buffer reuse: res1 -> g_k, x1 -> g_v, res2 -> g_q
    float* res1 = k;
    float* x1   = v;
    float* res2 = q;

    const dim3 blk(256);
    const dim3 grid_d (D_MODEL / BN, M_TOK / BM);   // (4, 512)
    const dim3 grid_ff(D_FF   / BN, M_TOK / BM);    // (16, 512)

    // 1) QKV projections
    sgemm_kernel<0><<<grid_d, blk>>>(x, Wq, bq, nullptr, q, M_TOK, D_MODEL, D_MODEL);
    sgemm_kernel<0><<<grid_d, blk>>>(x, Wk, bk, nullptr, k, M_TOK, D_MODEL, D_MODEL);
    sgemm_kernel<0><<<grid_d, blk>>>(x, Wv, bv, nullptr, v, M_TOK, D_MODEL, D_MODEL);

    // 2) Block-local window attention: (B*nW windows) * heads blocks
    const int n_blocks = (M_TOK / WINDOW) * N_HEADS;  // 2048 * 8 = 16384
    attn_kernel<<<n_blocks, blk>>>(q, k, v, o);

    // 3) Output projection + residual (res1 = o@Wo + bo + x), then LN1 -> x1
    sgemm_kernel<2><<<grid_d, blk>>>(o, Wo, bo, x, res1, M_TOK, D_MODEL, D_MODEL);
    ln_kernel<<<M_TOK / 8, blk>>>(res1, g1, be1, x1);

    // 4) FFN: h = relu(x1@W1 + b1); res2 = h@W2 + b2 + x1; LN2 -> out
    sgemm_kernel<1><<<grid_ff, blk>>>(x1, W1, b1, nullptr, h, M_TOK, D_FF, D_MODEL);
    sgemm_kernel<2><<<grid_d,  blk>>>(h,  W2, b2, x1,     res2, M_TOK, D_MODEL, D_FF);
    ln_kernel<<<M_TOK / 8, blk>>>(res2, g2, be2, out);
}

// round 15
// speedup vs baseline: 1.0003x; 1.0003x over previous
#include <cuda_runtime.h>
#include <cuda_bf16.h>
#include <cstddef>

// ---------------------------------------------------------------------------
// Problem constants
//   x: [8, 8192, 512] fp32, tokens M = 65536, D = 512, D_FF = 2048,
//   8 heads * dh=64, window = 32 (non-overlapping, block-local attention)
// ---------------------------------------------------------------------------
#define M_TOK   65536
#define D_MODEL 512
#define D_FF    2048
#define N_HEADS 8
#define D_HEAD  64
#define WINDOW  32
#define EPS_LN  1e-5f

// ---------------------------------------------------------------------------
// Device scratch (static device globals: allowed; no runtime allocation)
// ---------------------------------------------------------------------------
__device__ float g_q[M_TOK * D_MODEL];   // Q          ; reused for res2
__device__ float g_k[M_TOK * D_MODEL];   // K          ; reused for res1
__device__ float g_v[M_TOK * D_MODEL];   // V          ; reused for x1 (post-LN1)
__device__ float g_o[M_TOK * D_MODEL];   // attention output (pre-Wo)
__device__ float g_h[M_TOK * D_FF];      // FFN hidden

// ---------------------------------------------------------------------------
// SGEMM: C[M,N] = A[M,K] @ B[K,N] + bias (+ residual) (+ relu)
//   EPI 0: bias
//   EPI 1: bias + relu
//   EPI 2: bias + residual
// BM=BN=128, BK=16, 256 threads, 8x8 per thread.
// All M,N,K here are multiples of 128 -> no bounds checks.
// ---------------------------------------------------------------------------
#define BM 128
#define BN 128
#define BK 16
#define SPAD 136   // padded smem row length (conflict-free, float4-aligned)

template <int EPI>
__global__ __launch_bounds__(256, 2)
void sgemm_kernel(const float* __restrict__ A, const float* __restrict__ B,
                  const float* __restrict__ bias, const float* __restrict__ resid,
                  float* __restrict__ C, int M, int N, int K)
{
    __shared__ __align__(16) float As[BK][SPAD];  // stored transposed: As[k][m]
    __shared__ __align__(16) float Bs[BK][SPAD];  // Bs[k][n]

    const int tid = threadIdx.x;
    const int bm = blockIdx.y * BM;
    const int bn = blockIdx.x * BN;

    const int ty   = tid >> 4;        // 0..15
    const int tx   = tid & 15;        // 0..15
    const int row0 = ty * 8;          // 8 consecutive rows
    const int col0 = tx * 4;          // cols col0..+3 and col0+64..+67

    // A-tile load mapping: 128 rows x 16 cols, float4 along K
    const int ar = tid >> 2;          // 0..63
    const int ac = (tid & 3) * 4;     // 0,4,8,12
    // B-tile load mapping: 16 rows x 128 cols, float4 along N
    const int br = tid >> 5;          // 0..7
    const int bc = (tid & 31) * 4;    // 0..124

    float acc[8][8];
#pragma unroll
    for (int i = 0; i < 8; i++)
#pragma unroll
        for (int j = 0; j < 8; j++) acc[i][j] = 0.f;

    for (int kt = 0; kt < K; kt += BK) {
#pragma unroll
        for (int p = 0; p < 2; p++) {
            int r = ar + p * 64;
            float4 va = *reinterpret_cast<const float4*>(
                &A[(size_t)(bm + r) * K + kt + ac]);
            As[ac + 0][r] = va.x;
            As[ac + 1][r] = va.y;
            As[ac + 2][r] = va.z;
            As[ac + 3][r] = va.w;
        }
#pragma unroll
        for (int p = 0; p < 2; p++) {
            int r = br + p * 8;
            *reinterpret_cast<float4*>(&Bs[r][bc]) =
                *reinterpret_cast<const float4*>(
                    &B[(size_t)(kt + r) * N + bn + bc]);
        }
        __syncthreads();

#pragma unroll
        for (int k = 0; k < BK; k++) {
            float4 a0 = *reinterpret_cast<const float4*>(&As[k][row0]);
            float4 a1 = *reinterpret_cast<const float4*>(&As[k][row0 + 4]);
            float4 b0 = *reinterpret_cast<const float4*>(&Bs[k][col0]);
            float4 b1 = *reinterpret_cast<const float4*>(&Bs[k][col0 + 64]);
            float a[8] = {a0.x, a0.y, a0.z, a0.w, a1.x, a1.y, a1.z, a1.w};
            float b[8] = {b0.x, b0.y, b0.z, b0.w, b1.x, b1.y, b1.z, b1.w};
#pragma unroll
            for (int i = 0; i < 8; i++)
#pragma unroll
                for (int j = 0; j < 8; j++)
                    acc[i][j] = fmaf(a[i], b[j], acc[i][j]);
        }
        __syncthreads();
    }

    // Epilogue
    float bb[8];
#pragma unroll
    for (int j = 0; j < 4; j++) {
        bb[j]     = bias[bn + col0 + j];
        bb[4 + j] = bias[bn + col0 + 64 + j];
    }
#pragma unroll
    for (int i = 0; i < 8; i++) {
        size_t base = (size_t)(bm + row0 + i) * N + bn;
        float4 o0, o1;
        o0.x = acc[i][0] + bb[0]; o0.y = acc[i][1] + bb[1];
        o0.z = acc[i][2] + bb[2]; o0.w = acc[i][3] + bb[3];
        o1.x = acc[i][4] + bb[4]; o1.y = acc[i][5] + bb[5];
        o1.z = acc[i][6] + bb[6]; o1.w = acc[i][7] + bb[7];
        if (EPI == 2) {
            float4 r0 = *reinterpret_cast<const float4*>(&resid[base + col0]);
            float4 r1 = *reinterpret_cast<const float4*>(&resid[base + col0 + 64]);
            o0.x += r0.x; o0.y += r0.y; o0.z += r0.z; o0.w += r0.w;
            o1.x += r1.x; o1.y += r1.y; o1.z += r1.z; o1.w += r1.w;
        }
        if (EPI == 1) {
            o0.x = fmaxf(o0.x, 0.f); o0.y = fmaxf(o0.y, 0.f);
            o0.z = fmaxf(o0.z, 0.f); o0.w = fmaxf(o0.w, 0.f);
            o1.x = fmaxf(o1.x, 0.f); o1.y = fmaxf(o1.y, 0.f);
            o1.z = fmaxf(o1.z, 0.f); o1.w = fmaxf(o1.w, 0.f);
        }
        *reinterpret_cast<float4*>(&C[base + col0])      = o0;
        *reinterpret_cast<float4*>(&C[base + col0 + 64]) = o1;
    }
}

// ---------------------------------------------------------------------------
// Block-local window attention: one block per (window, head).
//   Q,K,V laid out as [token, 512] with head slice h*64..h*64+63.
//   scores = QK^T / sqrt(64), row-softmax, O = P V.
// ---------------------------------------------------------------------------
__global__ __launch_bounds__(256)
void attn_kernel(const float* __restrict__ Q, const float* __restrict__ K,
                 const float* __restrict__ V, float* __restrict__ O)
{
    __shared__ __align__(16) float qs[WINDOW * D_HEAD];
    __shared__ __align__(16) float ks[WINDOW * D_HEAD];
    __shared__ __align__(16) float vs[WINDOW * D_HEAD];
    __shared__ float sc[WINDOW][WINDOW + 1];

    const int tid = threadIdx.x;
    const int h   = blockIdx.x & (N_HEADS - 1);
    const int win = blockIdx.x >> 3;               // global window id (b*nW+n)
    const size_t t0 = (size_t)win * WINDOW;

    // Load Q/K/V tiles: 512 float4's each, 2 per thread
#pragma unroll
    for (int p = 0; p < 2; p++) {
        int v4 = tid + p * 256;        // 0..511
        int r  = v4 >> 4;              // 0..31
        int c4 = (v4 & 15) * 4;        // 0..60
        size_t gidx = (t0 + r) * D_MODEL + h * D_HEAD + c4;
        *reinterpret_cast<float4*>(&qs[r * D_HEAD + c4]) =
            *reinterpret_cast<const float4*>(&Q[gidx]);
        *reinterpret_cast<float4*>(&ks[r * D_HEAD + c4]) =
            *reinterpret_cast<const float4*>(&K[gidx]);
        *reinterpret_cast<float4*>(&vs[r * D_HEAD + c4]) =
            *reinterpret_cast<const float4*>(&V[gidx]);
    }
    __syncthreads();

    // Scores: 1024 entries, 4 per thread (same q-row, 4 consecutive k-rows)
    {
        int qr  = tid >> 3;            // 0..31
        int kr0 = (tid & 7) * 4;       // 0,4,...,28
        float s0 = 0.f, s1 = 0.f, s2 = 0.f, s3 = 0.f;
#pragma unroll
        for (int d = 0; d < D_HEAD; d += 4) {
            float4 qv = *reinterpret_cast<const float4*>(&qs[qr * D_HEAD + d]);
            float4 k0 = *reinterpret_cast<const float4*>(&ks[(kr0 + 0) * D_HEAD + d]);
            float4 k1 = *reinterpret_cast<const float4*>(&ks[(kr0 + 1) * D_HEAD + d]);
            float4 k2 = *reinterpret_cast<const float4*>(&ks[(kr0 + 2) * D_HEAD + d]);
            float4 k3 = *reinterpret_cast<const float4*>(&ks[(kr0 + 3) * D_HEAD + d]);
            s0 += qv.x * k0.x + qv.y * k0.y + qv.z * k0.z + qv.w * k0.w;
            s1 += qv.x * k1.x + qv.y * k1.y + qv.z * k1.z + qv.w * k1.w;
            s2 += qv.x * k2.x + qv.y * k2.y + qv.z * k2.z + qv.w * k2.w;
            s3 += qv.x * k3.x + qv.y * k3.y + qv.z * k3.z + qv.w * k3.w;
        }
        const float scale = 0.125f;    // 1/sqrt(64)
        sc[qr][kr0 + 0] = s0 * scale;
        sc[qr][kr0 + 1] = s1 * scale;
        sc[qr][kr0 + 2] = s2 * scale;
        sc[qr][kr0 + 3] = s3 * scale;
    }
    __syncthreads();

    // Softmax per row (rows are tiny: 32 entries; one thread per row)
    if (tid < WINDOW) {
        float mx = -1e30f;
#pragma unroll
        for (int j = 0; j < WINDOW; j++) mx = fmaxf(mx, sc[tid][j]);
        float s = 0.f;
#pragma unroll
        for (int j = 0; j < WINDOW; j++) {
            float e = __expf(sc[tid][j] - mx);
            sc[tid][j] = e;
            s += e;
        }
        float inv = 1.f / s;
#pragma unroll
        for (int j = 0; j < WINDOW; j++) sc[tid][j] *= inv;
    }
    __syncthreads();

    // O = P @ V : 512 float4 outputs, 2 per thread
#pragma unroll
    for (int p = 0; p < 2; p++) {
        int v4 = tid + p * 256;
        int qr = v4 >> 4;
        int c4 = (v4 & 15) * 4;
        float4 o = make_float4(0.f, 0.f, 0.f, 0.f);
#pragma unroll
        for (int kr = 0; kr < WINDOW; kr++) {
            float w = sc[qr][kr];
            float4 vv = *reinterpret_cast<const float4*>(&vs[kr * D_HEAD + c4]);
            o.x = fmaf(w, vv.x, o.x);
            o.y = fmaf(w, vv.y, o.y);
            o.z = fmaf(w, vv.z, o.z);
            o.w = fmaf(w, vv.w, o.w);
        }
        *reinterpret_cast<float4*>(&O[(t0 + qr) * D_MODEL + h * D_HEAD + c4]) = o;
    }
}

// ---------------------------------------------------------------------------
// LayerNorm over last dim (512). One warp per row, 8 rows per block.
// ---------------------------------------------------------------------------
__global__ __launch_bounds__(256)
void ln_kernel(const float* __restrict__ in, const float* __restrict__ g,
               const float* __restrict__ be, float* __restrict__ out)
{
    const int warp = threadIdx.x >> 5;
    const int lane = threadIdx.x & 31;
    const size_t row = (size_t)blockIdx.x * 8 + warp;
    const float* rp = in + row * D_MODEL;

    float4 xv[4];
    float s = 0.f, s2 = 0.f;
#pragma unroll
    for (int j = 0; j < 4; j++) {
        xv[j] = *reinterpret_cast<const float4*>(&rp[(lane + 32 * j) * 4]);
        s  += xv[j].x + xv[j].y + xv[j].z + xv[j].w;
        s2 += xv[j].x * xv[j].x + xv[j].y * xv[j].y +
              xv[j].z * xv[j].z + xv[j].w * xv[j].w;
    }
#pragma unroll
    for (int o = 16; o > 0; o >>= 1) {
        s  += __shfl_xor_sync(0xffffffffu, s,  o);
        s2 += __shfl_xor_sync(0xffffffffu, s2, o);
    }
    const float mu  = s * (1.f / D_MODEL);
    float var = s2 * (1.f / D_MODEL) - mu * mu;
    const float rs = rsqrtf(var + EPS_LN);

    float* op = out + row * D_MODEL;
#pragma unroll
    for (int j = 0; j < 4; j++) {
        int c = (lane + 32 * j) * 4;
        float4 gv = *reinterpret_cast<const float4*>(&g[c]);
        float4 bv = *reinterpret_cast<const float4*>(&be[c]);
        float4 y;
        y.x = (xv[j].x - mu) * rs * gv.x + bv.x;
        y.y = (xv[j].y - mu) * rs * gv.y + bv.y;
        y.z = (xv[j].z - mu) * rs * gv.z + bv.z;
        y.w = (xv[j].w - mu) * rs * gv.w + bv.w;
        *reinterpret_cast<float4*>(&op[c]) = y;
    }
}

// ---------------------------------------------------------------------------
// kernel_launch — graph-capturable: kernel launches on the default stream only
// ---------------------------------------------------------------------------
extern "C" void kernel_launch(void* const* d_in, const int* in_sizes, int n_in,
                              void* d_out, int out_size)
{
    const float* x   = (const float*)d_in[0];
    const float* Wq  = (const float*)d_in[1];
    const float* bq  = (const float*)d_in[2];
    const float* Wk  = (const float*)d_in[3];
    const float* bk  = (const float*)d_in[4];
    const float* Wv  = (const float*)d_in[5];
    const float* bv  = (const float*)d_in[6];
    const float* Wo  = (const float*)d_in[7];
    const float* bo  = (const float*)d_in[8];
    const float* g1  = (const float*)d_in[9];
    const float* be1 = (const float*)d_in[10];
    const float* W1  = (const float*)d_in[11];
    const float* b1  = (const float*)d_in[12];
    const float* W2  = (const float*)d_in[13];
    const float* b2  = (const float*)d_in[14];
    const float* g2  = (const float*)d_in[15];
    const float* be2 = (const float*)d_in[16];
    float* out = (float*)d_out;

    float *q, *k, *v, *o, *h;
    cudaGetSymbolAddress((void**)&q, g_q);
    cudaGetSymbolAddress((void**)&k, g_k);
    cudaGetSymbolAddress((void**)&v, g_v);
    cudaGetSymbolAddress((void**)&o, g_o);
    cudaGetSymbolAddress((void**)&h, g_h);

    // Buffer reuse: res1 -> g_k, x1 -> g_v, res2 -> g_q
    float* res1 = k;
    float* x1   = v;
    float* res2 = q;

    const dim3 blk(256);
    const dim3 grid_d (D_MODEL / BN, M_TOK / BM);   // (4, 512)
    const dim3 grid_ff(D_FF   / BN, M_TOK / BM);    // (16, 512)

    // 1) QKV projections
    sgemm_kernel<0><<<grid_d, blk>>>(x, Wq, bq, nullptr, q, M_TOK, D_MODEL, D_MODEL);
    sgemm_kernel<0><<<grid_d, blk>>>(x, Wk, bk, nullptr, k, M_TOK, D_MODEL, D_MODEL);
    sgemm_kernel<0><<<grid_d, blk>>>(x, Wv, bv, nullptr, v, M_TOK, D_MODEL, D_MODEL);

    // 2) Block-local window attention: (B*nW windows) * heads blocks
    const int n_blocks = (M_TOK / WINDOW) * N_HEADS;  // 2048 * 8 = 16384
    attn_kernel<<<n_blocks, blk>>>(q, k, v, o);

    // 3) Output projection + residual (res1 = o@Wo + bo + x), then LN1 -> x1
    sgemm_kernel<2><<<grid_d, blk>>>(o, Wo, bo, x, res1, M_TOK, D_MODEL, D_MODEL);
    ln_kernel<<<M_TOK / 8, blk>>>(res1, g1, be1, x1);

    // 4) FFN: h = relu(x1@W1 + b1); res2 = h@W2 + b2 + x1; LN2 -> out
    sgemm_kernel<1><<<grid_ff, blk>>>(x1, W1, b1, nullptr, h, M_TOK, D_FF, D_MODEL);
    sgemm_kernel<2><<<grid_d,  blk>>>(h,  W2, b2, x1,     res2, M_TOK, D_MODEL, D_FF);
    ln_kernel<<<M_TOK / 8, blk>>>(res2, g2, be2, out);
}